// round 5
// baseline (speedup 1.0000x reference)
#include <cuda_runtime.h>
#include <cstddef>

// Problem constants
#define BVAL 16
#define TVAL 2048
#define CVAL 1024
#define HVAL 64
#define QPITCH 68   // padded pitch (floats) for transposed smem tiles

// Scratch for Q/K/V projections: [B,T,H] each = 2M floats = 8MB
__device__ float g_q[BVAL * TVAL * HVAL];
__device__ float g_k[BVAL * TVAL * HVAL];
__device__ float g_v[BVAL * TVAL * HVAL];

// ---------------- packed f32x2 helpers (Blackwell FFMA2 path) ----------------
__device__ __forceinline__ unsigned long long ffma2(unsigned long long a,
                                                    unsigned long long b,
                                                    unsigned long long c) {
    unsigned long long d;
    asm("fma.rn.f32x2 %0, %1, %2, %3;" : "=l"(d) : "l"(a), "l"(b), "l"(c));
    return d;
}
__device__ __forceinline__ unsigned long long fmul2(unsigned long long a,
                                                    unsigned long long b) {
    unsigned long long d;
    asm("mul.rn.f32x2 %0, %1, %2;" : "=l"(d) : "l"(a), "l"(b));
    return d;
}
__device__ __forceinline__ unsigned long long pack2(float lo, float hi) {
    unsigned long long r;
    asm("mov.b64 %0, {%1, %2};" : "=l"(r) : "f"(lo), "f"(hi));
    return r;
}
__device__ __forceinline__ float2 unpack2(unsigned long long v) {
    float2 r;
    asm("mov.b64 {%0, %1}, %2;" : "=f"(r.x), "=f"(r.y) : "l"(v));
    return r;
}
__device__ __forceinline__ float ex2f(float x) {
    float y;
    asm("ex2.approx.ftz.f32 %0, %1;" : "=f"(y) : "f"(x));
    return y;
}

// ============================================================================
// Kernel 1: fused QKV projection.
// Each block: 64 rows of x (read once) x all 64 output cols x 3 weight mats.
// 256 threads (16x16), each thread: 4 rows x 4 cols x 3 mats, accumulated as
// f32x2 pairs (24 FFMA2 per inner iteration vs 4 LDS.128 -> fma-pipe bound).
// ============================================================================
__global__ void __launch_bounds__(256, 2)
qkv_kernel(const float* __restrict__ x, const float* __restrict__ wq,
           const float* __restrict__ wk, const float* __restrict__ wv) {
    __shared__ float xst[32][QPITCH];   // transposed x chunk: [k][row]
    __shared__ float ws[3][32][64];     // w chunks: [mat][k][col]

    const int tid = threadIdx.x;
    const int tx = tid & 15;            // col group
    const int ty = tid >> 4;            // row group
    const int row0 = blockIdx.x * 64;

    unsigned long long acc[3][4][2];
#pragma unroll
    for (int m = 0; m < 3; m++)
#pragma unroll
        for (int r = 0; r < 4; r++) { acc[m][r][0] = 0ull; acc[m][r][1] = 0ull; }

    for (int kc = 0; kc < CVAL; kc += 32) {
        __syncthreads();
        // load x[64][32] transposed into smem (coalesced float4 along k)
#pragma unroll
        for (int p = 0; p < 2; p++) {
            int idx = tid + p * 256;
            int r = idx >> 3, k4 = idx & 7;
            float4 xv = *reinterpret_cast<const float4*>(
                &x[(size_t)(row0 + r) * CVAL + kc + k4 * 4]);
            xst[k4 * 4 + 0][r] = xv.x;
            xst[k4 * 4 + 1][r] = xv.y;
            xst[k4 * 4 + 2][r] = xv.z;
            xst[k4 * 4 + 3][r] = xv.w;
        }
        // load 3 x w[32][64] chunks (fully coalesced float4)
#pragma unroll
        for (int p = 0; p < 6; p++) {
            int idx = tid + p * 256;
            int m = idx >> 9;
            int rem = idx & 511;
            int kk = rem >> 4, c4 = rem & 15;
            const float* wp = (m == 0) ? wq : ((m == 1) ? wk : wv);
            float4 wv4 = *reinterpret_cast<const float4*>(
                &wp[(size_t)(kc + kk) * HVAL + c4 * 4]);
            *reinterpret_cast<float4*>(&ws[m][kk][c4 * 4]) = wv4;
        }
        __syncthreads();

#pragma unroll 8
        for (int kk = 0; kk < 32; kk++) {
            float4 xv = *reinterpret_cast<const float4*>(&xst[kk][ty * 4]);
            unsigned long long xp[4] = {pack2(xv.x, xv.x), pack2(xv.y, xv.y),
                                        pack2(xv.z, xv.z), pack2(xv.w, xv.w)};
#pragma unroll
            for (int m = 0; m < 3; m++) {
                ulonglong2 wv =
                    *reinterpret_cast<const ulonglong2*>(&ws[m][kk][tx * 4]);
#pragma unroll
                for (int r = 0; r < 4; r++) {
                    acc[m][r][0] = ffma2(xp[r], wv.x, acc[m][r][0]);
                    acc[m][r][1] = ffma2(xp[r], wv.y, acc[m][r][1]);
                }
            }
        }
    }

#pragma unroll
    for (int m = 0; m < 3; m++) {
        float* op = (m == 0) ? g_q : ((m == 1) ? g_k : g_v);
#pragma unroll
        for (int r = 0; r < 4; r++) {
            float2 lo = unpack2(acc[m][r][0]);
            float2 hi = unpack2(acc[m][r][1]);
            float4 o = make_float4(lo.x, lo.y, hi.x, hi.y);
            *reinterpret_cast<float4*>(
                &op[(size_t)(row0 + ty * 4 + r) * HVAL + tx * 4]) = o;
        }
    }
}

// ============================================================================
// Kernel 2: causal flash attention, fp32, online softmax in base-2 domain.
// Block = (batch b, 64-query tile). Loops key tiles 0..qt (causal skip).
// 256 threads (16x16): S tile 64x64 = 4x4 per thread; O accum 4 rows x 4 cols
// kept in registers as f32x2 pairs. Heavy q-tiles launched first.
// ============================================================================
__global__ void __launch_bounds__(256, 2) attn_kernel(float* __restrict__ out) {
    extern __shared__ float sm[];
    float* qst = sm;                       // [64][QPITCH]  q' (pre-scaled), h-major
    float* kst = sm + 64 * QPITCH;         // [64][QPITCH]  k, h-major
    float* ps  = sm + 2 * 64 * QPITCH;     // [64][QPITCH]  P tile
    float* vs  = sm + 3 * 64 * QPITCH;     // [64][64]      V tile, row-major

    const int tid = threadIdx.x;
    const int tx = tid & 15;
    const int ty = tid >> 4;
    const int b = blockIdx.y;
    const int qt = (TVAL / 64 - 1) - blockIdx.x;   // heavy tiles first

    const float* qb = g_q + (size_t)b * TVAL * HVAL;
    const float* kb = g_k + (size_t)b * TVAL * HVAL;
    const float* vb = g_v + (size_t)b * TVAL * HVAL;

    // fold softmax scale (H^-0.5 = 0.125) and log2(e) into Q once
    const float sc = 0.125f * 1.4426950408889634f;

    // load Q tile transposed + scaled
#pragma unroll
    for (int p = 0; p < 4; p++) {
        int idx = tid + p * 256;
        int i = idx >> 4, h4 = idx & 15;
        float4 qv = *reinterpret_cast<const float4*>(
            &qb[(size_t)(qt * 64 + i) * HVAL + h4 * 4]);
        qst[(h4 * 4 + 0) * QPITCH + i] = qv.x * sc;
        qst[(h4 * 4 + 1) * QPITCH + i] = qv.y * sc;
        qst[(h4 * 4 + 2) * QPITCH + i] = qv.z * sc;
        qst[(h4 * 4 + 3) * QPITCH + i] = qv.w * sc;
    }

    unsigned long long oacc[4][2];
    float mrow[4], lrow[4];
#pragma unroll
    for (int r = 0; r < 4; r++) {
        oacc[r][0] = 0ull; oacc[r][1] = 0ull;
        mrow[r] = -1e30f;  lrow[r] = 0.0f;
    }

    for (int kt = 0; kt <= qt; kt++) {
        __syncthreads();   // guards qst (1st iter) + kst/vs reuse (later iters)
        // load K tile transposed + V tile direct
#pragma unroll
        for (int p = 0; p < 4; p++) {
            int idx = tid + p * 256;
            int j = idx >> 4, h4 = idx & 15;
            float4 kv = *reinterpret_cast<const float4*>(
                &kb[(size_t)(kt * 64 + j) * HVAL + h4 * 4]);
            kst[(h4 * 4 + 0) * QPITCH + j] = kv.x;
            kst[(h4 * 4 + 1) * QPITCH + j] = kv.y;
            kst[(h4 * 4 + 2) * QPITCH + j] = kv.z;
            kst[(h4 * 4 + 3) * QPITCH + j] = kv.w;
            float4 vv = *reinterpret_cast<const float4*>(
                &vb[(size_t)(kt * 64 + j) * HVAL + h4 * 4]);
            *reinterpret_cast<float4*>(&vs[j * 64 + h4 * 4]) = vv;
        }
        __syncthreads();

        // ---- GEMM1: S = Q' K^T (log2-domain scores) ----
        unsigned long long sacc[4][2];
#pragma unroll
        for (int r = 0; r < 4; r++) { sacc[r][0] = 0ull; sacc[r][1] = 0ull; }
#pragma unroll 8
        for (int h = 0; h < 64; h++) {
            float4 qv = *reinterpret_cast<const float4*>(&qst[h * QPITCH + ty * 4]);
            ulonglong2 kv =
                *reinterpret_cast<const ulonglong2*>(&kst[h * QPITCH + tx * 4]);
            float q4[4] = {qv.x, qv.y, qv.z, qv.w};
#pragma unroll
            for (int r = 0; r < 4; r++) {
                unsigned long long qp = pack2(q4[r], q4[r]);
                sacc[r][0] = ffma2(qp, kv.x, sacc[r][0]);
                sacc[r][1] = ffma2(qp, kv.y, sacc[r][1]);
            }
        }
        float s[4][4];
#pragma unroll
        for (int r = 0; r < 4; r++) {
            float2 a = unpack2(sacc[r][0]);
            float2 c = unpack2(sacc[r][1]);
            s[r][0] = a.x; s[r][1] = a.y; s[r][2] = c.x; s[r][3] = c.y;
        }

        // causal mask (only the diagonal tile needs it)
        if (kt == qt) {
#pragma unroll
            for (int r = 0; r < 4; r++) {
                int gi = ty * 4 + r;
#pragma unroll
                for (int c = 0; c < 4; c++) {
                    int gj = tx * 4 + c;
                    if (gj > gi) s[r][c] = -1e30f;
                }
            }
        }

        // ---- online softmax update ----
#pragma unroll
        for (int r = 0; r < 4; r++) {
            float rm = fmaxf(fmaxf(s[r][0], s[r][1]), fmaxf(s[r][2], s[r][3]));
            rm = fmaxf(rm, __shfl_xor_sync(0xffffffffu, rm, 8));
            rm = fmaxf(rm, __shfl_xor_sync(0xffffffffu, rm, 4));
            rm = fmaxf(rm, __shfl_xor_sync(0xffffffffu, rm, 2));
            rm = fmaxf(rm, __shfl_xor_sync(0xffffffffu, rm, 1));
            float mnew = fmaxf(mrow[r], rm);
            float alpha = ex2f(mrow[r] - mnew);
            float p0 = ex2f(s[r][0] - mnew);
            float p1 = ex2f(s[r][1] - mnew);
            float p2 = ex2f(s[r][2] - mnew);
            float p3 = ex2f(s[r][3] - mnew);
            float rs = (p0 + p1) + (p2 + p3);
            rs += __shfl_xor_sync(0xffffffffu, rs, 8);
            rs += __shfl_xor_sync(0xffffffffu, rs, 4);
            rs += __shfl_xor_sync(0xffffffffu, rs, 2);
            rs += __shfl_xor_sync(0xffffffffu, rs, 1);
            lrow[r] = lrow[r] * alpha + rs;
            mrow[r] = mnew;
            float4 pv = make_float4(p0, p1, p2, p3);
            *reinterpret_cast<float4*>(&ps[(ty * 4 + r) * QPITCH + tx * 4]) = pv;
            unsigned long long a2 = pack2(alpha, alpha);
            oacc[r][0] = fmul2(oacc[r][0], a2);
            oacc[r][1] = fmul2(oacc[r][1], a2);
        }
        __syncthreads();

        // ---- GEMM2: O += P V ----
#pragma unroll 8
        for (int j = 0; j < 64; j++) {
            ulonglong2 vv =
                *reinterpret_cast<const ulonglong2*>(&vs[j * 64 + tx * 4]);
#pragma unroll
            for (int r = 0; r < 4; r++) {
                float pj = ps[(ty * 4 + r) * QPITCH + j];
                unsigned long long pp = pack2(pj, pj);
                oacc[r][0] = ffma2(pp, vv.x, oacc[r][0]);
                oacc[r][1] = ffma2(pp, vv.y, oacc[r][1]);
            }
        }
    }

    // normalize and write out [B,T,H]
#pragma unroll
    for (int r = 0; r < 4; r++) {
        float inv = 1.0f / lrow[r];
        float2 a = unpack2(oacc[r][0]);
        float2 c = unpack2(oacc[r][1]);
        float4 o = make_float4(a.x * inv, a.y * inv, c.x * inv, c.y * inv);
        *reinterpret_cast<float4*>(
            &out[(size_t)(b * TVAL + qt * 64 + ty * 4 + r) * HVAL + tx * 4]) = o;
    }
}

// ============================================================================
// kernel_launch: projection kernel then attention kernel (same stream, graph-
// capturable: kernel launches + one idempotent attribute set only).
// ============================================================================
extern "C" void kernel_launch(void* const* d_in, const int* in_sizes, int n_in,
                              void* d_out, int out_size) {
    (void)in_sizes; (void)n_in; (void)out_size;
    const float* x  = (const float*)d_in[0];
    const float* wq = (const float*)d_in[1];
    const float* wk = (const float*)d_in[2];
    const float* wv = (const float*)d_in[3];
    float* out = (float*)d_out;

    qkv_kernel<<<(BVAL * TVAL) / 64, 256>>>(x, wq, wk, wv);

    const int smem_bytes = (3 * 64 * QPITCH + 64 * 64) * (int)sizeof(float); // 68608
    // Idempotent; already applied by the (non-captured) correctness call, so a
    // no-op during graph capture. Ignore return value by design.
    cudaFuncSetAttribute(attn_kernel,
                         cudaFuncAttributeMaxDynamicSharedMemorySize, smem_bytes);
    dim3 grid(TVAL / 64, BVAL);
    attn_kernel<<<grid, 256, smem_bytes>>>(out);
}

// round 10
// speedup vs baseline: 1.3537x; 1.3537x over previous
#include <cuda_runtime.h>
#include <cuda_bf16.h>
#include <cstddef>
#include <cstdint>

// Problem constants
#define BVAL 16
#define TVAL 2048
#define CVAL 1024
#define HVAL 64
#define QPITCH 68   // padded pitch (floats) for transposed smem tiles

// Scratch: Q/K/V projections [B,T,H] fp32, + split weights [192][1024] bf16
__device__ float g_q[BVAL * TVAL * HVAL];
__device__ float g_k[BVAL * TVAL * HVAL];
__device__ float g_v[BVAL * TVAL * HVAL];
__device__ __nv_bfloat16 g_whi[192 * CVAL];
__device__ __nv_bfloat16 g_wlo[192 * CVAL];

// ---------------- packed f32x2 helpers (attn kernel) ----------------
__device__ __forceinline__ unsigned long long ffma2(unsigned long long a,
                                                    unsigned long long b,
                                                    unsigned long long c) {
    unsigned long long d;
    asm("fma.rn.f32x2 %0, %1, %2, %3;" : "=l"(d) : "l"(a), "l"(b), "l"(c));
    return d;
}
__device__ __forceinline__ unsigned long long fmul2(unsigned long long a,
                                                    unsigned long long b) {
    unsigned long long d;
    asm("mul.rn.f32x2 %0, %1, %2;" : "=l"(d) : "l"(a), "l"(b));
    return d;
}
__device__ __forceinline__ unsigned long long pack2(float lo, float hi) {
    unsigned long long r;
    asm("mov.b64 %0, {%1, %2};" : "=l"(r) : "f"(lo), "f"(hi));
    return r;
}
__device__ __forceinline__ float2 unpack2(unsigned long long v) {
    float2 r;
    asm("mov.b64 {%0, %1}, %2;" : "=f"(r.x), "=f"(r.y) : "l"(v));
    return r;
}
__device__ __forceinline__ float ex2f(float x) {
    float y;
    asm("ex2.approx.ftz.f32 %0, %1;" : "=f"(y) : "f"(x));
    return y;
}

// ---------------- bf16 split helpers ----------------
__device__ __forceinline__ uint32_t bfpair(float lo, float hi) {
    uint32_t r;
    asm("cvt.rn.bf16x2.f32 %0, %1, %2;" : "=r"(r) : "f"(hi), "f"(lo));
    return r;
}
__device__ __forceinline__ float bf_lo(uint32_t h) {
    return __uint_as_float(h << 16);
}
__device__ __forceinline__ float bf_hi(uint32_t h) {
    return __uint_as_float(h & 0xffff0000u);
}

// ---------------- mma.sync / ldmatrix helpers (base-ISA, sm_80+) ------------
__device__ __forceinline__ uint32_t smem_u32(const void* p) {
    uint32_t a;
    asm("{ .reg .u64 t; cvta.to.shared.u64 t, %1; cvt.u32.u64 %0, t; }"
        : "=r"(a) : "l"(p));
    return a;
}
__device__ __forceinline__ void ldsm_x4(uint32_t addr, uint32_t* r) {
    asm volatile(
        "ldmatrix.sync.aligned.m8n8.x4.shared.b16 {%0,%1,%2,%3}, [%4];"
        : "=r"(r[0]), "=r"(r[1]), "=r"(r[2]), "=r"(r[3]) : "r"(addr));
}
__device__ __forceinline__ void mma_bf16(float* d, const uint32_t* a,
                                         const uint32_t* b) {
    asm volatile(
        "mma.sync.aligned.m16n8k16.row.col.f32.bf16.bf16.f32 "
        "{%0,%1,%2,%3}, {%4,%5,%6,%7}, {%8,%9}, {%0,%1,%2,%3};"
        : "+f"(d[0]), "+f"(d[1]), "+f"(d[2]), "+f"(d[3])
        : "r"(a[0]), "r"(a[1]), "r"(a[2]), "r"(a[3]), "r"(b[0]), "r"(b[1]));
}

// ============================================================================
// Kernel 0: split weights into bf16 hi/lo, fused layout B[192][1024]
// (rows 0-63 = w_q cols, 64-127 = w_k, 128-191 = w_v; K-major = col-major B)
// ============================================================================
__global__ void conv_w_kernel(const float* __restrict__ wq,
                              const float* __restrict__ wk,
                              const float* __restrict__ wv) {
    int idx = blockIdx.x * 256 + threadIdx.x;   // 0 .. 192*1024-1
    int n = idx >> 10, k = idx & 1023;
    const float* wp = (n < 64) ? wq : ((n < 128) ? wk : wv);
    float val = wp[(size_t)k * HVAL + (n & 63)];
    __nv_bfloat16 hi = __float2bfloat16(val);
    __nv_bfloat16 lo = __float2bfloat16(val - __bfloat162float(hi));
    g_whi[idx] = hi;
    g_wlo[idx] = lo;
}

// ============================================================================
// Kernel 1: QKV projection via mma.sync bf16-split HMMA.
// CTA: 128 rows (M) x 192 cols (N=q|k|v), K=1024 in 16 chunks of 64.
// 8 warps = 4(M) x 2(N); warp tile 32M x 96N; frags m16n8k16.
// 3 MMA terms: Ahi*Bhi + Ahi*Blo + Alo*Bhi (err ~2^-17).
// Smem pitch 144B (9 x 16B) -> conflict-free ldmatrix row addressing.
// ============================================================================
#define APITCH 144                      // bytes per smem row (64 bf16 + pad)
#define OFF_AHI 0
#define OFF_ALO (128 * APITCH)          // 18432
#define OFF_BHI (2 * 128 * APITCH)      // 36864
#define OFF_BLO (OFF_BHI + 192 * APITCH)
#define QKV_SMEM (OFF_BLO + 192 * APITCH)   // 92160 bytes

__global__ void __launch_bounds__(256, 1)
qkv_gemm(const float* __restrict__ x) {
    extern __shared__ char dsm[];
    const uint32_t sbase = smem_u32(dsm);
    const int tid = threadIdx.x;
    const int lane = tid & 31;
    const int wid = tid >> 5;
    const int warp_m = wid & 3;         // 4 M-tiles of 32
    const int warp_n = wid >> 2;        // 2 N-tiles of 96
    const int row0 = blockIdx.x * 128;

    float acc[2][12][4];
#pragma unroll
    for (int m = 0; m < 2; m++)
#pragma unroll
        for (int j = 0; j < 12; j++)
#pragma unroll
            for (int e = 0; e < 4; e++) acc[m][j][e] = 0.0f;

    // per-lane ldmatrix base addresses (add ks*32 + tile offsets in the loop)
    const uint32_t aAddr =
        sbase + OFF_AHI + (warp_m * 32 + (lane & 15)) * APITCH +
        (lane >> 4) * 16;
    const uint32_t bAddr =
        sbase + OFF_BHI +
        (warp_n * 96 + ((lane >> 4) & 1) * 8 + (lane & 7)) * APITCH +
        ((lane >> 3) & 1) * 16;

    for (int c = 0; c < 16; c++) {
        const int kc = c * 64;
        __syncthreads();
        // --- A: x[128][64] fp32 -> bf16 hi/lo into smem (pitch 144B) ---
#pragma unroll
        for (int p = 0; p < 8; p++) {
            int u = tid + p * 256;          // 0..2047 float4 units
            int r = u >> 4, c4 = u & 15;
            float4 a = *reinterpret_cast<const float4*>(
                &x[(size_t)(row0 + r) * CVAL + kc + c4 * 4]);
            uint32_t h0 = bfpair(a.x, a.y), h1 = bfpair(a.z, a.w);
            uint32_t l0 = bfpair(a.x - bf_lo(h0), a.y - bf_hi(h0));
            uint32_t l1 = bfpair(a.z - bf_lo(h1), a.w - bf_hi(h1));
            char* dst = dsm + r * APITCH + c4 * 8;
            *reinterpret_cast<uint2*>(dst + OFF_AHI) = make_uint2(h0, h1);
            *reinterpret_cast<uint2*>(dst + OFF_ALO) = make_uint2(l0, l1);
        }
        // --- B: w chunks [192][64] bf16 hi/lo into smem ---
#pragma unroll
        for (int p = 0; p < 12; p++) {
            int u = tid + p * 256;          // 0..3071 (16B units)
            int v = (u < 1536) ? u : u - 1536;
            const __nv_bfloat16* src = (u < 1536) ? g_whi : g_wlo;
            int boff = (u < 1536) ? OFF_BHI : OFF_BLO;
            int n = v >> 3, c8 = v & 7;
            uint4 d = *reinterpret_cast<const uint4*>(
                src + (size_t)n * CVAL + kc + c8 * 8);
            *reinterpret_cast<uint4*>(dsm + boff + n * APITCH + c8 * 16) = d;
        }
        __syncthreads();

#pragma unroll
        for (int ks = 0; ks < 4; ks++) {
            const uint32_t kb = ks * 32;
            uint32_t ah[2][4], al[2][4];
            ldsm_x4(aAddr + kb, ah[0]);
            ldsm_x4(aAddr + kb + 16 * APITCH, ah[1]);
            ldsm_x4(aAddr + kb + (OFF_ALO - OFF_AHI), al[0]);
            ldsm_x4(aAddr + kb + (OFF_ALO - OFF_AHI) + 16 * APITCH, al[1]);
            uint32_t bh[24], bl[24];
#pragma unroll
            for (int jp = 0; jp < 6; jp++) {
                ldsm_x4(bAddr + kb + jp * 16 * APITCH, &bh[jp * 4]);
                ldsm_x4(bAddr + kb + (OFF_BLO - OFF_BHI) + jp * 16 * APITCH,
                        &bl[jp * 4]);
            }
#pragma unroll
            for (int m = 0; m < 2; m++)
#pragma unroll
                for (int j = 0; j < 12; j++) {
                    mma_bf16(acc[m][j], ah[m], &bh[j * 2]);
                    mma_bf16(acc[m][j], ah[m], &bl[j * 2]);
                    mma_bf16(acc[m][j], al[m], &bh[j * 2]);
                }
        }
    }

    // --- epilogue: scatter accum frags to g_q / g_k / g_v ---
    const int r_in = lane >> 2;
    const int c_in = (lane & 3) * 2;
#pragma unroll
    for (int m = 0; m < 2; m++) {
        int grow = row0 + warp_m * 32 + m * 16 + r_in;
#pragma unroll
        for (int j = 0; j < 12; j++) {
            int j8 = warp_n * 96 + j * 8;
            float* base = (j8 < 64) ? g_q : ((j8 < 128) ? g_k : g_v);
            int col = (j8 & 63) + c_in;
            *reinterpret_cast<float2*>(&base[(size_t)grow * HVAL + col]) =
                make_float2(acc[m][j][0], acc[m][j][1]);
            *reinterpret_cast<float2*>(&base[(size_t)(grow + 8) * HVAL + col]) =
                make_float2(acc[m][j][2], acc[m][j][3]);
        }
    }
}

// ============================================================================
// Kernel 2: causal flash attention, fp32, online softmax in base-2 domain.
// (unchanged — isolates the HMMA QKV change)
// ============================================================================
__global__ void __launch_bounds__(256, 2) attn_kernel(float* __restrict__ out) {
    extern __shared__ float sm[];
    float* qst = sm;                       // [64][QPITCH]  q' (pre-scaled), h-major
    float* kst = sm + 64 * QPITCH;         // [64][QPITCH]  k, h-major
    float* ps  = sm + 2 * 64 * QPITCH;     // [64][QPITCH]  P tile
    float* vs  = sm + 3 * 64 * QPITCH;     // [64][64]      V tile, row-major

    const int tid = threadIdx.x;
    const int tx = tid & 15;
    const int ty = tid >> 4;
    const int b = blockIdx.y;
    const int qt = (TVAL / 64 - 1) - blockIdx.x;   // heavy tiles first

    const float* qb = g_q + (size_t)b * TVAL * HVAL;
    const float* kb = g_k + (size_t)b * TVAL * HVAL;
    const float* vb = g_v + (size_t)b * TVAL * HVAL;

    // fold softmax scale (H^-0.5 = 0.125) and log2(e) into Q once
    const float sc = 0.125f * 1.4426950408889634f;

    // load Q tile transposed + scaled
#pragma unroll
    for (int p = 0; p < 4; p++) {
        int idx = tid + p * 256;
        int i = idx >> 4, h4 = idx & 15;
        float4 qv = *reinterpret_cast<const float4*>(
            &qb[(size_t)(qt * 64 + i) * HVAL + h4 * 4]);
        qst[(h4 * 4 + 0) * QPITCH + i] = qv.x * sc;
        qst[(h4 * 4 + 1) * QPITCH + i] = qv.y * sc;
        qst[(h4 * 4 + 2) * QPITCH + i] = qv.z * sc;
        qst[(h4 * 4 + 3) * QPITCH + i] = qv.w * sc;
    }

    unsigned long long oacc[4][2];
    float mrow[4], lrow[4];
#pragma unroll
    for (int r = 0; r < 4; r++) {
        oacc[r][0] = 0ull; oacc[r][1] = 0ull;
        mrow[r] = -1e30f;  lrow[r] = 0.0f;
    }

    for (int kt = 0; kt <= qt; kt++) {
        __syncthreads();   // guards qst (1st iter) + kst/vs reuse (later iters)
        // load K tile transposed + V tile direct
#pragma unroll
        for (int p = 0; p < 4; p++) {
            int idx = tid + p * 256;
            int j = idx >> 4, h4 = idx & 15;
            float4 kv = *reinterpret_cast<const float4*>(
                &kb[(size_t)(kt * 64 + j) * HVAL + h4 * 4]);
            kst[(h4 * 4 + 0) * QPITCH + j] = kv.x;
            kst[(h4 * 4 + 1) * QPITCH + j] = kv.y;
            kst[(h4 * 4 + 2) * QPITCH + j] = kv.z;
            kst[(h4 * 4 + 3) * QPITCH + j] = kv.w;
            float4 vv = *reinterpret_cast<const float4*>(
                &vb[(size_t)(kt * 64 + j) * HVAL + h4 * 4]);
            *reinterpret_cast<float4*>(&vs[j * 64 + h4 * 4]) = vv;
        }
        __syncthreads();

        // ---- GEMM1: S = Q' K^T (log2-domain scores) ----
        unsigned long long sacc[4][2];
#pragma unroll
        for (int r = 0; r < 4; r++) { sacc[r][0] = 0ull; sacc[r][1] = 0ull; }
#pragma unroll 8
        for (int h = 0; h < 64; h++) {
            float4 qv = *reinterpret_cast<const float4*>(&qst[h * QPITCH + ty * 4]);
            ulonglong2 kv =
                *reinterpret_cast<const ulonglong2*>(&kst[h * QPITCH + tx * 4]);
            float q4[4] = {qv.x, qv.y, qv.z, qv.w};
#pragma unroll
            for (int r = 0; r < 4; r++) {
                unsigned long long qp = pack2(q4[r], q4[r]);
                sacc[r][0] = ffma2(qp, kv.x, sacc[r][0]);
                sacc[r][1] = ffma2(qp, kv.y, sacc[r][1]);
            }
        }
        float s[4][4];
#pragma unroll
        for (int r = 0; r < 4; r++) {
            float2 a = unpack2(sacc[r][0]);
            float2 c = unpack2(sacc[r][1]);
            s[r][0] = a.x; s[r][1] = a.y; s[r][2] = c.x; s[r][3] = c.y;
        }

        // causal mask (only the diagonal tile needs it)
        if (kt == qt) {
#pragma unroll
            for (int r = 0; r < 4; r++) {
                int gi = ty * 4 + r;
#pragma unroll
                for (int c = 0; c < 4; c++) {
                    int gj = tx * 4 + c;
                    if (gj > gi) s[r][c] = -1e30f;
                }
            }
        }

        // ---- online softmax update ----
#pragma unroll
        for (int r = 0; r < 4; r++) {
            float rm = fmaxf(fmaxf(s[r][0], s[r][1]), fmaxf(s[r][2], s[r][3]));
            rm = fmaxf(rm, __shfl_xor_sync(0xffffffffu, rm, 8));
            rm = fmaxf(rm, __shfl_xor_sync(0xffffffffu, rm, 4));
            rm = fmaxf(rm, __shfl_xor_sync(0xffffffffu, rm, 2));
            rm = fmaxf(rm, __shfl_xor_sync(0xffffffffu, rm, 1));
            float mnew = fmaxf(mrow[r], rm);
            float alpha = ex2f(mrow[r] - mnew);
            float p0 = ex2f(s[r][0] - mnew);
            float p1 = ex2f(s[r][1] - mnew);
            float p2 = ex2f(s[r][2] - mnew);
            float p3 = ex2f(s[r][3] - mnew);
            float rs = (p0 + p1) + (p2 + p3);
            rs += __shfl_xor_sync(0xffffffffu, rs, 8);
            rs += __shfl_xor_sync(0xffffffffu, rs, 4);
            rs += __shfl_xor_sync(0xffffffffu, rs, 2);
            rs += __shfl_xor_sync(0xffffffffu, rs, 1);
            lrow[r] = lrow[r] * alpha + rs;
            mrow[r] = mnew;
            float4 pv = make_float4(p0, p1, p2, p3);
            *reinterpret_cast<float4*>(&ps[(ty * 4 + r) * QPITCH + tx * 4]) = pv;
            unsigned long long a2 = pack2(alpha, alpha);
            oacc[r][0] = fmul2(oacc[r][0], a2);
            oacc[r][1] = fmul2(oacc[r][1], a2);
        }
        __syncthreads();

        // ---- GEMM2: O += P V ----
#pragma unroll 8
        for (int j = 0; j < 64; j++) {
            ulonglong2 vv =
                *reinterpret_cast<const ulonglong2*>(&vs[j * 64 + tx * 4]);
#pragma unroll
            for (int r = 0; r < 4; r++) {
                float pj = ps[(ty * 4 + r) * QPITCH + j];
                unsigned long long pp = pack2(pj, pj);
                oacc[r][0] = ffma2(pp, vv.x, oacc[r][0]);
                oacc[r][1] = ffma2(pp, vv.y, oacc[r][1]);
            }
        }
    }

    // normalize and write out [B,T,H]
#pragma unroll
    for (int r = 0; r < 4; r++) {
        float inv = 1.0f / lrow[r];
        float2 a = unpack2(oacc[r][0]);
        float2 c = unpack2(oacc[r][1]);
        float4 o = make_float4(a.x * inv, a.y * inv, c.x * inv, c.y * inv);
        *reinterpret_cast<float4*>(
            &out[(size_t)(b * TVAL + qt * 64 + ty * 4 + r) * HVAL + tx * 4]) = o;
    }
}

// ============================================================================
// kernel_launch: w-split, HMMA QKV GEMM, then fp32 flash attention.
// ============================================================================
extern "C" void kernel_launch(void* const* d_in, const int* in_sizes, int n_in,
                              void* d_out, int out_size) {
    (void)in_sizes; (void)n_in; (void)out_size;
    const float* x  = (const float*)d_in[0];
    const float* wq = (const float*)d_in[1];
    const float* wk = (const float*)d_in[2];
    const float* wv = (const float*)d_in[3];
    float* out = (float*)d_out;

    conv_w_kernel<<<(192 * CVAL) / 256, 256>>>(wq, wk, wv);

    cudaFuncSetAttribute(qkv_gemm,
                         cudaFuncAttributeMaxDynamicSharedMemorySize, QKV_SMEM);
    qkv_gemm<<<(BVAL * TVAL) / 128, 256, QKV_SMEM>>>(x);

    const int smem_bytes = (3 * 64 * QPITCH + 64 * 64) * (int)sizeof(float); // 68608
    cudaFuncSetAttribute(attn_kernel,
                         cudaFuncAttributeMaxDynamicSharedMemorySize, smem_bytes);
    dim3 grid(TVAL / 64, BVAL);
    attn_kernel<<<grid, 256, smem_bytes>>>(out);
}

// round 11
// speedup vs baseline: 2.8416x; 2.0992x over previous
#include <cuda_runtime.h>
#include <cuda_bf16.h>
#include <cstddef>
#include <cstdint>

// Problem constants
#define BVAL 16
#define TVAL 2048
#define CVAL 1024
#define HVAL 64

// Split weights [192][1024] bf16 (rows 0-63 wq, 64-127 wk, 128-191 wv; K-major)
__device__ __nv_bfloat16 g_whi[192 * CVAL];
__device__ __nv_bfloat16 g_wlo[192 * CVAL];
// Split projections [B*T*H] bf16 hi/lo (Q pre-scaled by 0.125*log2e)
__device__ __nv_bfloat16 g_qhi[BVAL * TVAL * HVAL];
__device__ __nv_bfloat16 g_qlo[BVAL * TVAL * HVAL];
__device__ __nv_bfloat16 g_khi[BVAL * TVAL * HVAL];
__device__ __nv_bfloat16 g_klo[BVAL * TVAL * HVAL];
__device__ __nv_bfloat16 g_vhi[BVAL * TVAL * HVAL];
__device__ __nv_bfloat16 g_vlo[BVAL * TVAL * HVAL];

// ---------------- helpers ----------------
__device__ __forceinline__ float ex2f(float x) {
    float y;
    asm("ex2.approx.ftz.f32 %0, %1;" : "=f"(y) : "f"(x));
    return y;
}
__device__ __forceinline__ uint32_t bfpair(float lo, float hi) {
    uint32_t r;
    asm("cvt.rn.bf16x2.f32 %0, %1, %2;" : "=r"(r) : "f"(hi), "f"(lo));
    return r;
}
__device__ __forceinline__ float bf_lo(uint32_t h) {
    return __uint_as_float(h << 16);
}
__device__ __forceinline__ float bf_hi(uint32_t h) {
    return __uint_as_float(h & 0xffff0000u);
}
__device__ __forceinline__ uint32_t smem_u32(const void* p) {
    uint32_t a;
    asm("{ .reg .u64 t; cvta.to.shared.u64 t, %1; cvt.u32.u64 %0, t; }"
        : "=r"(a) : "l"(p));
    return a;
}
__device__ __forceinline__ void ldsm_x4(uint32_t addr, uint32_t* r) {
    asm volatile(
        "ldmatrix.sync.aligned.m8n8.x4.shared.b16 {%0,%1,%2,%3}, [%4];"
        : "=r"(r[0]), "=r"(r[1]), "=r"(r[2]), "=r"(r[3]) : "r"(addr));
}
__device__ __forceinline__ void ldsm_x4_t(uint32_t addr, uint32_t* r) {
    asm volatile(
        "ldmatrix.sync.aligned.m8n8.x4.trans.shared.b16 {%0,%1,%2,%3}, [%4];"
        : "=r"(r[0]), "=r"(r[1]), "=r"(r[2]), "=r"(r[3]) : "r"(addr));
}
__device__ __forceinline__ void mma_bf16(float* d, const uint32_t* a,
                                         const uint32_t* b) {
    asm volatile(
        "mma.sync.aligned.m16n8k16.row.col.f32.bf16.bf16.f32 "
        "{%0,%1,%2,%3}, {%4,%5,%6,%7}, {%8,%9}, {%0,%1,%2,%3};"
        : "+f"(d[0]), "+f"(d[1]), "+f"(d[2]), "+f"(d[3])
        : "r"(a[0]), "r"(a[1]), "r"(a[2]), "r"(a[3]), "r"(b[0]), "r"(b[1]));
}

// ============================================================================
// Kernel 0: split weights into bf16 hi/lo
// ============================================================================
__global__ void conv_w_kernel(const float* __restrict__ wq,
                              const float* __restrict__ wk,
                              const float* __restrict__ wv) {
    int idx = blockIdx.x * 256 + threadIdx.x;   // 0 .. 192*1024-1
    int n = idx >> 10, k = idx & 1023;
    const float* wp = (n < 64) ? wq : ((n < 128) ? wk : wv);
    float val = wp[(size_t)k * HVAL + (n & 63)];
    __nv_bfloat16 hi = __float2bfloat16(val);
    __nv_bfloat16 lo = __float2bfloat16(val - __bfloat162float(hi));
    g_whi[idx] = hi;
    g_wlo[idx] = lo;
}

// ============================================================================
// Kernel 1: QKV projection via mma.sync bf16-split HMMA.
// CTA: 128M x 192N (q|k|v), K=1024 in 16 chunks of 64. 8 warps = 4M x 2N.
// Epilogue writes bf16 hi/lo Q/K/V (Q pre-scaled by 0.125*log2e).
// ============================================================================
#define APITCH 144                      // bytes per smem row (64 bf16 + pad)
#define OFF_AHI 0
#define OFF_ALO (128 * APITCH)
#define OFF_BHI (2 * 128 * APITCH)
#define OFF_BLO (OFF_BHI + 192 * APITCH)
#define QKV_SMEM (OFF_BLO + 192 * APITCH)   // 92160 bytes

__global__ void __launch_bounds__(256, 1)
qkv_gemm(const float* __restrict__ x) {
    extern __shared__ char dsm[];
    const uint32_t sbase = smem_u32(dsm);
    const int tid = threadIdx.x;
    const int lane = tid & 31;
    const int wid = tid >> 5;
    const int warp_m = wid & 3;
    const int warp_n = wid >> 2;
    const int row0 = blockIdx.x * 128;

    float acc[2][12][4];
#pragma unroll
    for (int m = 0; m < 2; m++)
#pragma unroll
        for (int j = 0; j < 12; j++)
#pragma unroll
            for (int e = 0; e < 4; e++) acc[m][j][e] = 0.0f;

    const uint32_t aAddr =
        sbase + OFF_AHI + (warp_m * 32 + (lane & 15)) * APITCH +
        (lane >> 4) * 16;
    const uint32_t bAddr =
        sbase + OFF_BHI +
        (warp_n * 96 + ((lane >> 4) & 1) * 8 + (lane & 7)) * APITCH +
        ((lane >> 3) & 1) * 16;

    for (int c = 0; c < 16; c++) {
        const int kc = c * 64;
        __syncthreads();
#pragma unroll
        for (int p = 0; p < 8; p++) {
            int u = tid + p * 256;
            int r = u >> 4, c4 = u & 15;
            float4 a = *reinterpret_cast<const float4*>(
                &x[(size_t)(row0 + r) * CVAL + kc + c4 * 4]);
            uint32_t h0 = bfpair(a.x, a.y), h1 = bfpair(a.z, a.w);
            uint32_t l0 = bfpair(a.x - bf_lo(h0), a.y - bf_hi(h0));
            uint32_t l1 = bfpair(a.z - bf_lo(h1), a.w - bf_hi(h1));
            char* dst = dsm + r * APITCH + c4 * 8;
            *reinterpret_cast<uint2*>(dst + OFF_AHI) = make_uint2(h0, h1);
            *reinterpret_cast<uint2*>(dst + OFF_ALO) = make_uint2(l0, l1);
        }
#pragma unroll
        for (int p = 0; p < 12; p++) {
            int u = tid + p * 256;
            int v = (u < 1536) ? u : u - 1536;
            const __nv_bfloat16* src = (u < 1536) ? g_whi : g_wlo;
            int boff = (u < 1536) ? OFF_BHI : OFF_BLO;
            int n = v >> 3, c8 = v & 7;
            uint4 d = *reinterpret_cast<const uint4*>(
                src + (size_t)n * CVAL + kc + c8 * 8);
            *reinterpret_cast<uint4*>(dsm + boff + n * APITCH + c8 * 16) = d;
        }
        __syncthreads();

#pragma unroll
        for (int ks = 0; ks < 4; ks++) {
            const uint32_t kb = ks * 32;
            uint32_t ah[2][4], al[2][4];
            ldsm_x4(aAddr + kb, ah[0]);
            ldsm_x4(aAddr + kb + 16 * APITCH, ah[1]);
            ldsm_x4(aAddr + kb + (OFF_ALO - OFF_AHI), al[0]);
            ldsm_x4(aAddr + kb + (OFF_ALO - OFF_AHI) + 16 * APITCH, al[1]);
            uint32_t bh[24], bl[24];
#pragma unroll
            for (int jp = 0; jp < 6; jp++) {
                ldsm_x4(bAddr + kb + jp * 16 * APITCH, &bh[jp * 4]);
                ldsm_x4(bAddr + kb + (OFF_BLO - OFF_BHI) + jp * 16 * APITCH,
                        &bl[jp * 4]);
            }
#pragma unroll
            for (int m = 0; m < 2; m++)
#pragma unroll
                for (int j = 0; j < 12; j++) {
                    mma_bf16(acc[m][j], ah[m], &bh[j * 2]);
                    mma_bf16(acc[m][j], ah[m], &bl[j * 2]);
                    mma_bf16(acc[m][j], al[m], &bh[j * 2]);
                }
        }
    }

    // --- epilogue: split to bf16 hi/lo, scatter to g_q/g_k/g_v hi/lo ---
    const float qsc = 0.125f * 1.4426950408889634f;
    const int r_in = lane >> 2;
    const int c_in = (lane & 3) * 2;
#pragma unroll
    for (int m = 0; m < 2; m++) {
        int grow = row0 + warp_m * 32 + m * 16 + r_in;
#pragma unroll
        for (int j = 0; j < 12; j++) {
            int j8 = warp_n * 96 + j * 8;
            __nv_bfloat16* hi = (j8 < 64) ? g_qhi : ((j8 < 128) ? g_khi : g_vhi);
            __nv_bfloat16* lo = (j8 < 64) ? g_qlo : ((j8 < 128) ? g_klo : g_vlo);
            float scl = (j8 < 64) ? qsc : 1.0f;
            int col = (j8 & 63) + c_in;
            float v0 = acc[m][j][0] * scl, v1 = acc[m][j][1] * scl;
            float v2 = acc[m][j][2] * scl, v3 = acc[m][j][3] * scl;
            uint32_t h01 = bfpair(v0, v1);
            uint32_t l01 = bfpair(v0 - bf_lo(h01), v1 - bf_hi(h01));
            uint32_t h23 = bfpair(v2, v3);
            uint32_t l23 = bfpair(v2 - bf_lo(h23), v3 - bf_hi(h23));
            size_t i0 = (size_t)grow * HVAL + col;
            size_t i1 = (size_t)(grow + 8) * HVAL + col;
            *reinterpret_cast<uint32_t*>(&hi[i0]) = h01;
            *reinterpret_cast<uint32_t*>(&lo[i0]) = l01;
            *reinterpret_cast<uint32_t*>(&hi[i1]) = h23;
            *reinterpret_cast<uint32_t*>(&lo[i1]) = l23;
        }
    }
}

// ============================================================================
// Kernel 2: causal flash attention via mma.sync bf16-split HMMA.
// CTA: 64 queries, 4 warps x 16 rows; key tiles of 64; softmax per-warp in
// registers (base-2 domain; Q pre-scaled). P repacked C-frag->A-frag in regs.
// 3-term splits in both GEMMs (err ~2^-17).
// ============================================================================
#define PITCH 144
#define AT_QHI 0
#define AT_QLO (64 * PITCH)
#define AT_KHI (2 * 64 * PITCH)
#define AT_KLO (3 * 64 * PITCH)
#define AT_VHI (4 * 64 * PITCH)
#define AT_VLO (5 * 64 * PITCH)
#define ATTN_SMEM (6 * 64 * PITCH)   // 55296 bytes

__global__ void __launch_bounds__(128)
attn_hmma(float* __restrict__ out) {
    extern __shared__ char dsm[];
    const uint32_t sbase = smem_u32(dsm);
    const int tid = threadIdx.x;
    const int lane = tid & 31;
    const int w = tid >> 5;
    const int b = blockIdx.y;
    const int qt = (TVAL / 64 - 1) - blockIdx.x;   // heavy tiles first
    const size_t base = (size_t)b * TVAL * HVAL;

    // ---- load Q tiles (hi/lo), once ----
    {
        const uint4* sh = reinterpret_cast<const uint4*>(
            g_qhi + base + (size_t)qt * 64 * HVAL);
        const uint4* sl = reinterpret_cast<const uint4*>(
            g_qlo + base + (size_t)qt * 64 * HVAL);
#pragma unroll
        for (int p = 0; p < 4; p++) {
            int u = tid + p * 128;          // 0..511 (16B units)
            int r = u >> 3, c8 = u & 7;
            char* dst = dsm + r * PITCH + c8 * 16;
            *reinterpret_cast<uint4*>(dst + AT_QHI) = sh[u];
            *reinterpret_cast<uint4*>(dst + AT_QLO) = sl[u];
        }
    }

    const uint32_t qAddr =
        sbase + AT_QHI + (w * 16 + (lane & 15)) * PITCH + (lane >> 4) * 16;
    const uint32_t kAddr =
        sbase + AT_KHI + (((lane >> 4) & 1) * 8 + (lane & 7)) * PITCH +
        ((lane >> 3) & 1) * 16;
    const uint32_t vAddr =
        sbase + AT_VHI + (lane & 15) * PITCH + (lane >> 4) * 16;

    float oacc[8][4];
#pragma unroll
    for (int n = 0; n < 8; n++)
#pragma unroll
        for (int e = 0; e < 4; e++) oacc[n][e] = 0.0f;
    float m0 = -1e30f, m1 = -1e30f, l0 = 0.0f, l1 = 0.0f;

    for (int kt = 0; kt <= qt; kt++) {
        __syncthreads();
        // ---- load K/V tiles (hi/lo) ----
        {
            size_t toff = base + (size_t)kt * 64 * HVAL;
            const uint4* kh = reinterpret_cast<const uint4*>(g_khi + toff);
            const uint4* kl = reinterpret_cast<const uint4*>(g_klo + toff);
            const uint4* vh = reinterpret_cast<const uint4*>(g_vhi + toff);
            const uint4* vl = reinterpret_cast<const uint4*>(g_vlo + toff);
#pragma unroll
            for (int p = 0; p < 4; p++) {
                int u = tid + p * 128;
                int r = u >> 3, c8 = u & 7;
                char* dst = dsm + r * PITCH + c8 * 16;
                *reinterpret_cast<uint4*>(dst + AT_KHI) = kh[u];
                *reinterpret_cast<uint4*>(dst + AT_KLO) = kl[u];
                *reinterpret_cast<uint4*>(dst + AT_VHI) = vh[u];
                *reinterpret_cast<uint4*>(dst + AT_VLO) = vl[u];
            }
        }
        __syncthreads();

        // ---- GEMM1: S = Q' K^T ----
        float s[8][4];
#pragma unroll
        for (int n = 0; n < 8; n++)
#pragma unroll
            for (int e = 0; e < 4; e++) s[n][e] = 0.0f;
#pragma unroll
        for (int t = 0; t < 4; t++) {
            uint32_t ah[4], al[4];
            ldsm_x4(qAddr + t * 32, ah);
            ldsm_x4(qAddr + t * 32 + (AT_QLO - AT_QHI), al);
            uint32_t kh[16], kl[16];
#pragma unroll
            for (int jp = 0; jp < 4; jp++) {
                ldsm_x4(kAddr + t * 32 + jp * 16 * PITCH, &kh[jp * 4]);
                ldsm_x4(kAddr + t * 32 + (AT_KLO - AT_KHI) + jp * 16 * PITCH,
                        &kl[jp * 4]);
            }
#pragma unroll
            for (int n = 0; n < 8; n++) {
                mma_bf16(s[n], ah, &kh[n * 2]);
                mma_bf16(s[n], ah, &kl[n * 2]);
                mma_bf16(s[n], al, &kh[n * 2]);
            }
        }

        // ---- causal mask (diagonal tile only) ----
        const int rl0 = w * 16 + (lane >> 2);
        if (kt == qt) {
#pragma unroll
            for (int n = 0; n < 8; n++) {
                int c = n * 8 + (lane & 3) * 2;
                if (c > rl0) s[n][0] = -1e30f;
                if (c + 1 > rl0) s[n][1] = -1e30f;
                if (c > rl0 + 8) s[n][2] = -1e30f;
                if (c + 1 > rl0 + 8) s[n][3] = -1e30f;
            }
        }

        // ---- online softmax (per-warp, registers only) ----
        float mx0 = -1e30f, mx1 = -1e30f;
#pragma unroll
        for (int n = 0; n < 8; n++) {
            mx0 = fmaxf(mx0, fmaxf(s[n][0], s[n][1]));
            mx1 = fmaxf(mx1, fmaxf(s[n][2], s[n][3]));
        }
        mx0 = fmaxf(mx0, __shfl_xor_sync(0xffffffffu, mx0, 1));
        mx0 = fmaxf(mx0, __shfl_xor_sync(0xffffffffu, mx0, 2));
        mx1 = fmaxf(mx1, __shfl_xor_sync(0xffffffffu, mx1, 1));
        mx1 = fmaxf(mx1, __shfl_xor_sync(0xffffffffu, mx1, 2));
        float mn0 = fmaxf(m0, mx0), mn1 = fmaxf(m1, mx1);
        float a0 = ex2f(m0 - mn0), a1 = ex2f(m1 - mn1);
        float sum0 = 0.0f, sum1 = 0.0f;
#pragma unroll
        for (int n = 0; n < 8; n++) {
            s[n][0] = ex2f(s[n][0] - mn0);
            s[n][1] = ex2f(s[n][1] - mn0);
            s[n][2] = ex2f(s[n][2] - mn1);
            s[n][3] = ex2f(s[n][3] - mn1);
            sum0 += s[n][0] + s[n][1];
            sum1 += s[n][2] + s[n][3];
        }
        sum0 += __shfl_xor_sync(0xffffffffu, sum0, 1);
        sum0 += __shfl_xor_sync(0xffffffffu, sum0, 2);
        sum1 += __shfl_xor_sync(0xffffffffu, sum1, 1);
        sum1 += __shfl_xor_sync(0xffffffffu, sum1, 2);
        l0 = l0 * a0 + sum0;
        l1 = l1 * a1 + sum1;
        m0 = mn0;
        m1 = mn1;
#pragma unroll
        for (int n = 0; n < 8; n++) {
            oacc[n][0] *= a0;
            oacc[n][1] *= a0;
            oacc[n][2] *= a1;
            oacc[n][3] *= a1;
        }

        // ---- repack P: C-frag -> A-frags (bf16 hi/lo), registers only ----
        uint32_t pah[4][4], pal[4][4];
#pragma unroll
        for (int t = 0; t < 4; t++) {
            pah[t][0] = bfpair(s[2 * t][0], s[2 * t][1]);
            pah[t][1] = bfpair(s[2 * t][2], s[2 * t][3]);
            pah[t][2] = bfpair(s[2 * t + 1][0], s[2 * t + 1][1]);
            pah[t][3] = bfpair(s[2 * t + 1][2], s[2 * t + 1][3]);
            pal[t][0] = bfpair(s[2 * t][0] - bf_lo(pah[t][0]),
                               s[2 * t][1] - bf_hi(pah[t][0]));
            pal[t][1] = bfpair(s[2 * t][2] - bf_lo(pah[t][1]),
                               s[2 * t][3] - bf_hi(pah[t][1]));
            pal[t][2] = bfpair(s[2 * t + 1][0] - bf_lo(pah[t][2]),
                               s[2 * t + 1][1] - bf_hi(pah[t][2]));
            pal[t][3] = bfpair(s[2 * t + 1][2] - bf_lo(pah[t][3]),
                               s[2 * t + 1][3] - bf_hi(pah[t][3]));
        }

        // ---- GEMM2: O += P V ----
#pragma unroll
        for (int t = 0; t < 4; t++) {
            uint32_t vh[16], vl[16];
#pragma unroll
            for (int jp = 0; jp < 4; jp++) {
                ldsm_x4_t(vAddr + t * 16 * PITCH + jp * 32, &vh[jp * 4]);
                ldsm_x4_t(vAddr + t * 16 * PITCH + (AT_VLO - AT_VHI) + jp * 32,
                          &vl[jp * 4]);
            }
#pragma unroll
            for (int n = 0; n < 8; n++) {
                mma_bf16(oacc[n], pah[t], &vh[n * 2]);
                mma_bf16(oacc[n], pal[t], &vh[n * 2]);
                mma_bf16(oacc[n], pah[t], &vl[n * 2]);
            }
        }
    }

    // ---- epilogue: normalize, write fp32 out [B,T,H] ----
    float i0 = 1.0f / l0, i1 = 1.0f / l1;
    int grow = b * TVAL + qt * 64 + w * 16 + (lane >> 2);
#pragma unroll
    for (int n = 0; n < 8; n++) {
        int col = n * 8 + (lane & 3) * 2;
        *reinterpret_cast<float2*>(&out[(size_t)grow * HVAL + col]) =
            make_float2(oacc[n][0] * i0, oacc[n][1] * i0);
        *reinterpret_cast<float2*>(&out[(size_t)(grow + 8) * HVAL + col]) =
            make_float2(oacc[n][2] * i1, oacc[n][3] * i1);
    }
}

// ============================================================================
// kernel_launch
// ============================================================================
extern "C" void kernel_launch(void* const* d_in, const int* in_sizes, int n_in,
                              void* d_out, int out_size) {
    (void)in_sizes; (void)n_in; (void)out_size;
    const float* x  = (const float*)d_in[0];
    const float* wq = (const float*)d_in[1];
    const float* wk = (const float*)d_in[2];
    const float* wv = (const float*)d_in[3];
    float* out = (float*)d_out;

    conv_w_kernel<<<(192 * CVAL) / 256, 256>>>(wq, wk, wv);

    cudaFuncSetAttribute(qkv_gemm,
                         cudaFuncAttributeMaxDynamicSharedMemorySize, QKV_SMEM);
    qkv_gemm<<<(BVAL * TVAL) / 128, 256, QKV_SMEM>>>(x);

    cudaFuncSetAttribute(attn_hmma,
                         cudaFuncAttributeMaxDynamicSharedMemorySize, ATTN_SMEM);
    dim3 grid(TVAL / 64, BVAL);
    attn_hmma<<<grid, 128, ATTN_SMEM>>>(out);
}

// round 12
// speedup vs baseline: 2.8864x; 1.0158x over previous
#include <cuda_runtime.h>
#include <cuda_bf16.h>
#include <cstddef>
#include <cstdint>

// Problem constants
#define BVAL 16
#define TVAL 2048
#define CVAL 1024
#define HVAL 64

// Split weights [192][1024] bf16 (rows 0-63 wq, 64-127 wk, 128-191 wv; K-major)
__device__ __nv_bfloat16 g_whi[192 * CVAL];
__device__ __nv_bfloat16 g_wlo[192 * CVAL];
// Split projections [B*T*H] bf16 hi/lo (Q pre-scaled by 0.125*log2e)
__device__ __nv_bfloat16 g_qhi[BVAL * TVAL * HVAL];
__device__ __nv_bfloat16 g_qlo[BVAL * TVAL * HVAL];
__device__ __nv_bfloat16 g_khi[BVAL * TVAL * HVAL];
__device__ __nv_bfloat16 g_klo[BVAL * TVAL * HVAL];
__device__ __nv_bfloat16 g_vhi[BVAL * TVAL * HVAL];
__device__ __nv_bfloat16 g_vlo[BVAL * TVAL * HVAL];

// ---------------- helpers ----------------
__device__ __forceinline__ float ex2f(float x) {
    float y;
    asm("ex2.approx.ftz.f32 %0, %1;" : "=f"(y) : "f"(x));
    return y;
}
__device__ __forceinline__ uint32_t bfpair(float lo, float hi) {
    uint32_t r;
    asm("cvt.rn.bf16x2.f32 %0, %1, %2;" : "=r"(r) : "f"(hi), "f"(lo));
    return r;
}
__device__ __forceinline__ float bf_lo(uint32_t h) {
    return __uint_as_float(h << 16);
}
__device__ __forceinline__ float bf_hi(uint32_t h) {
    return __uint_as_float(h & 0xffff0000u);
}
__device__ __forceinline__ uint32_t smem_u32(const void* p) {
    uint32_t a;
    asm("{ .reg .u64 t; cvta.to.shared.u64 t, %1; cvt.u32.u64 %0, t; }"
        : "=r"(a) : "l"(p));
    return a;
}
__device__ __forceinline__ void ldsm_x4(uint32_t addr, uint32_t* r) {
    asm volatile(
        "ldmatrix.sync.aligned.m8n8.x4.shared.b16 {%0,%1,%2,%3}, [%4];"
        : "=r"(r[0]), "=r"(r[1]), "=r"(r[2]), "=r"(r[3]) : "r"(addr));
}
__device__ __forceinline__ void ldsm_x4_t(uint32_t addr, uint32_t* r) {
    asm volatile(
        "ldmatrix.sync.aligned.m8n8.x4.trans.shared.b16 {%0,%1,%2,%3}, [%4];"
        : "=r"(r[0]), "=r"(r[1]), "=r"(r[2]), "=r"(r[3]) : "r"(addr));
}
__device__ __forceinline__ void mma_bf16(float* d, const uint32_t* a,
                                         const uint32_t* b) {
    asm volatile(
        "mma.sync.aligned.m16n8k16.row.col.f32.bf16.bf16.f32 "
        "{%0,%1,%2,%3}, {%4,%5,%6,%7}, {%8,%9}, {%0,%1,%2,%3};"
        : "+f"(d[0]), "+f"(d[1]), "+f"(d[2]), "+f"(d[3])
        : "r"(a[0]), "r"(a[1]), "r"(a[2]), "r"(a[3]), "r"(b[0]), "r"(b[1]));
}
__device__ __forceinline__ void cp16(uint32_t dst, const void* src) {
    asm volatile("cp.async.cg.shared.global [%0], [%1], 16;"
                 :: "r"(dst), "l"(src));
}
__device__ __forceinline__ void cp_commit() {
    asm volatile("cp.async.commit_group;");
}
__device__ __forceinline__ void cp_wait0() {
    asm volatile("cp.async.wait_group 0;" ::: "memory");
}

// ============================================================================
// Kernel 0: split weights into bf16 hi/lo
// ============================================================================
__global__ void conv_w_kernel(const float* __restrict__ wq,
                              const float* __restrict__ wk,
                              const float* __restrict__ wv) {
    int idx = blockIdx.x * 256 + threadIdx.x;   // 0 .. 192*1024-1
    int n = idx >> 10, k = idx & 1023;
    const float* wp = (n < 64) ? wq : ((n < 128) ? wk : wv);
    float val = wp[(size_t)k * HVAL + (n & 63)];
    __nv_bfloat16 hi = __float2bfloat16(val);
    __nv_bfloat16 lo = __float2bfloat16(val - __bfloat162float(hi));
    g_whi[idx] = hi;
    g_wlo[idx] = lo;
}

// ============================================================================
// Kernel 1: QKV projection via mma.sync bf16-split HMMA, double-buffered.
// CTA: 128M x 192N (q|k|v), K=1024 in 16 chunks of 64. 8 warps = 4M x 2N.
// Per chunk: cp.async B(c+1) + LDG-prefetch A(c+1) -> regs, MMA on stage c,
// convert+store A(c+1), ONE syncthreads. Epilogue writes bf16 hi/lo Q/K/V.
// ============================================================================
#define APITCH 144                      // bytes per smem row (64 bf16 + pad)
#define OFF_AHI 0
#define OFF_ALO (128 * APITCH)
#define OFF_BHI (2 * 128 * APITCH)
#define OFF_BLO (OFF_BHI + 192 * APITCH)
#define STAGE (OFF_BLO + 192 * APITCH)      // 92160 bytes per stage
#define QKV_SMEM (2 * STAGE)                // 184320 bytes

__device__ __forceinline__ void qkv_load_B_async(uint32_t stb, int kc,
                                                 int tid) {
#pragma unroll
    for (int p = 0; p < 12; p++) {
        int u = tid + p * 256;
        int v = (u < 1536) ? u : u - 1536;
        const __nv_bfloat16* src = (u < 1536) ? g_whi : g_wlo;
        uint32_t boff = (u < 1536) ? OFF_BHI : OFF_BLO;
        int n = v >> 3, c8 = v & 7;
        cp16(stb + boff + n * APITCH + c8 * 16,
             src + (size_t)n * CVAL + kc + c8 * 8);
    }
}
__device__ __forceinline__ void qkv_load_A_regs(const float* __restrict__ x,
                                                int row0, int kc, int tid,
                                                float4* a) {
#pragma unroll
    for (int p = 0; p < 8; p++) {
        int u = tid + p * 256;
        int r = u >> 4, c4 = u & 15;
        a[p] = *reinterpret_cast<const float4*>(
            &x[(size_t)(row0 + r) * CVAL + kc + c4 * 4]);
    }
}
__device__ __forceinline__ void qkv_store_A(char* stage, int tid,
                                            const float4* a) {
#pragma unroll
    for (int p = 0; p < 8; p++) {
        int u = tid + p * 256;
        int r = u >> 4, c4 = u & 15;
        uint32_t h0 = bfpair(a[p].x, a[p].y), h1 = bfpair(a[p].z, a[p].w);
        uint32_t l0 = bfpair(a[p].x - bf_lo(h0), a[p].y - bf_hi(h0));
        uint32_t l1 = bfpair(a[p].z - bf_lo(h1), a[p].w - bf_hi(h1));
        char* dst = stage + r * APITCH + c4 * 8;
        *reinterpret_cast<uint2*>(dst + OFF_AHI) = make_uint2(h0, h1);
        *reinterpret_cast<uint2*>(dst + OFF_ALO) = make_uint2(l0, l1);
    }
}

__global__ void __launch_bounds__(256, 1)
qkv_gemm(const float* __restrict__ x) {
    extern __shared__ char dsm[];
    const uint32_t sbase = smem_u32(dsm);
    const int tid = threadIdx.x;
    const int lane = tid & 31;
    const int wid = tid >> 5;
    const int warp_m = wid & 3;
    const int warp_n = wid >> 2;
    const int row0 = blockIdx.x * 128;

    float acc[2][12][4];
#pragma unroll
    for (int m = 0; m < 2; m++)
#pragma unroll
        for (int j = 0; j < 12; j++)
#pragma unroll
            for (int e = 0; e < 4; e++) acc[m][j][e] = 0.0f;

    // stage-relative ldmatrix offsets
    const uint32_t aOff =
        OFF_AHI + (warp_m * 32 + (lane & 15)) * APITCH + (lane >> 4) * 16;
    const uint32_t bOff =
        OFF_BHI + (warp_n * 96 + ((lane >> 4) & 1) * 8 + (lane & 7)) * APITCH +
        ((lane >> 3) & 1) * 16;

    float4 areg[8];
    // prologue: chunk 0 into stage 0
    qkv_load_A_regs(x, row0, 0, tid, areg);
    qkv_load_B_async(sbase, 0, tid);
    cp_commit();
    qkv_store_A(dsm, tid, areg);
    cp_wait0();
    __syncthreads();

    for (int c = 0; c < 16; c++) {
        const uint32_t stb = sbase + (uint32_t)(c & 1) * STAGE;
        const uint32_t nstb = sbase + (uint32_t)((c & 1) ^ 1) * STAGE;
        char* nxt = dsm + ((c & 1) ^ 1) * STAGE;
        if (c < 15) {
            qkv_load_B_async(nstb, (c + 1) * 64, tid);
            cp_commit();
            qkv_load_A_regs(x, row0, (c + 1) * 64, tid, areg);
        }

        const uint32_t aAddr = stb + aOff;
        const uint32_t bAddr = stb + bOff;
#pragma unroll
        for (int ks = 0; ks < 4; ks++) {
            const uint32_t kb = ks * 32;
            uint32_t ah[2][4], al[2][4];
            ldsm_x4(aAddr + kb, ah[0]);
            ldsm_x4(aAddr + kb + 16 * APITCH, ah[1]);
            ldsm_x4(aAddr + kb + (OFF_ALO - OFF_AHI), al[0]);
            ldsm_x4(aAddr + kb + (OFF_ALO - OFF_AHI) + 16 * APITCH, al[1]);
#pragma unroll
            for (int jp = 0; jp < 6; jp++) {
                uint32_t bh4[4], bl4[4];
                ldsm_x4(bAddr + kb + jp * 16 * APITCH, bh4);
                ldsm_x4(bAddr + kb + (OFF_BLO - OFF_BHI) + jp * 16 * APITCH,
                        bl4);
#pragma unroll
                for (int m = 0; m < 2; m++)
#pragma unroll
                    for (int jj = 0; jj < 2; jj++) {
                        int j = jp * 2 + jj;
                        mma_bf16(acc[m][j], ah[m], &bh4[jj * 2]);
                        mma_bf16(acc[m][j], ah[m], &bl4[jj * 2]);
                        mma_bf16(acc[m][j], al[m], &bh4[jj * 2]);
                    }
            }
        }

        if (c < 15) qkv_store_A(nxt, tid, areg);
        cp_wait0();
        __syncthreads();
    }

    // --- epilogue: split to bf16 hi/lo, scatter to g_q/g_k/g_v hi/lo ---
    const float qsc = 0.125f * 1.4426950408889634f;
    const int r_in = lane >> 2;
    const int c_in = (lane & 3) * 2;
#pragma unroll
    for (int m = 0; m < 2; m++) {
        int grow = row0 + warp_m * 32 + m * 16 + r_in;
#pragma unroll
        for (int j = 0; j < 12; j++) {
            int j8 = warp_n * 96 + j * 8;
            __nv_bfloat16* hi = (j8 < 64) ? g_qhi : ((j8 < 128) ? g_khi : g_vhi);
            __nv_bfloat16* lo = (j8 < 64) ? g_qlo : ((j8 < 128) ? g_klo : g_vlo);
            float scl = (j8 < 64) ? qsc : 1.0f;
            int col = (j8 & 63) + c_in;
            float v0 = acc[m][j][0] * scl, v1 = acc[m][j][1] * scl;
            float v2 = acc[m][j][2] * scl, v3 = acc[m][j][3] * scl;
            uint32_t h01 = bfpair(v0, v1);
            uint32_t l01 = bfpair(v0 - bf_lo(h01), v1 - bf_hi(h01));
            uint32_t h23 = bfpair(v2, v3);
            uint32_t l23 = bfpair(v2 - bf_lo(h23), v3 - bf_hi(h23));
            size_t i0 = (size_t)grow * HVAL + col;
            size_t i1 = (size_t)(grow + 8) * HVAL + col;
            *reinterpret_cast<uint32_t*>(&hi[i0]) = h01;
            *reinterpret_cast<uint32_t*>(&lo[i0]) = l01;
            *reinterpret_cast<uint32_t*>(&hi[i1]) = h23;
            *reinterpret_cast<uint32_t*>(&lo[i1]) = l23;
        }
    }
}

// ============================================================================
// Kernel 2: causal flash attention via mma.sync bf16-split HMMA,
// double-buffered K/V via cp.async. CTA: 64 queries, 4 warps x 16 rows.
// ============================================================================
#define PITCH 144
#define AT_QHI 0
#define AT_QLO (64 * PITCH)
#define STAGE0_OFF (2 * 64 * PITCH)     // 18432
#define ST_KHI 0
#define ST_KLO (64 * PITCH)
#define ST_VHI (2 * 64 * PITCH)
#define ST_VLO (3 * 64 * PITCH)
#define ST_SIZE (4 * 64 * PITCH)        // 36864
#define ATTN_SMEM (STAGE0_OFF + 2 * ST_SIZE)   // 92160 bytes

__device__ __forceinline__ void attn_load_kv_async(uint32_t stb, size_t toff,
                                                   int tid) {
    const uint4* kh = reinterpret_cast<const uint4*>(g_khi + toff);
    const uint4* kl = reinterpret_cast<const uint4*>(g_klo + toff);
    const uint4* vh = reinterpret_cast<const uint4*>(g_vhi + toff);
    const uint4* vl = reinterpret_cast<const uint4*>(g_vlo + toff);
#pragma unroll
    for (int p = 0; p < 4; p++) {
        int u = tid + p * 128;
        int r = u >> 3, c8 = u & 7;
        uint32_t d = stb + r * PITCH + c8 * 16;
        cp16(d + ST_KHI, kh + u);
        cp16(d + ST_KLO, kl + u);
        cp16(d + ST_VHI, vh + u);
        cp16(d + ST_VLO, vl + u);
    }
}

__global__ void __launch_bounds__(128)
attn_hmma(float* __restrict__ out) {
    extern __shared__ char dsm[];
    const uint32_t sbase = smem_u32(dsm);
    const int tid = threadIdx.x;
    const int lane = tid & 31;
    const int w = tid >> 5;
    const int b = blockIdx.y;
    const int qt = (TVAL / 64 - 1) - blockIdx.x;   // heavy tiles first
    const size_t base = (size_t)b * TVAL * HVAL;

    // ---- prologue: load Q tiles (hi/lo) + first K/V stage ----
    attn_load_kv_async(sbase + STAGE0_OFF, base, tid);
    cp_commit();
    {
        const uint4* sh = reinterpret_cast<const uint4*>(
            g_qhi + base + (size_t)qt * 64 * HVAL);
        const uint4* sl = reinterpret_cast<const uint4*>(
            g_qlo + base + (size_t)qt * 64 * HVAL);
#pragma unroll
        for (int p = 0; p < 4; p++) {
            int u = tid + p * 128;          // 0..511 (16B units)
            int r = u >> 3, c8 = u & 7;
            char* dst = dsm + r * PITCH + c8 * 16;
            *reinterpret_cast<uint4*>(dst + AT_QHI) = sh[u];
            *reinterpret_cast<uint4*>(dst + AT_QLO) = sl[u];
        }
    }
    cp_wait0();
    __syncthreads();

    const uint32_t qAddr =
        sbase + AT_QHI + (w * 16 + (lane & 15)) * PITCH + (lane >> 4) * 16;
    const uint32_t kOff =
        ST_KHI + (((lane >> 4) & 1) * 8 + (lane & 7)) * PITCH +
        ((lane >> 3) & 1) * 16;
    const uint32_t vOff =
        ST_VHI + (lane & 15) * PITCH + (lane >> 4) * 16;

    float oacc[8][4];
#pragma unroll
    for (int n = 0; n < 8; n++)
#pragma unroll
        for (int e = 0; e < 4; e++) oacc[n][e] = 0.0f;
    float m0 = -1e30f, m1 = -1e30f, l0 = 0.0f, l1 = 0.0f;

    for (int kt = 0; kt <= qt; kt++) {
        const uint32_t stb = sbase + STAGE0_OFF + (uint32_t)(kt & 1) * ST_SIZE;
        if (kt < qt) {
            attn_load_kv_async(
                sbase + STAGE0_OFF + (uint32_t)((kt & 1) ^ 1) * ST_SIZE,
                base + (size_t)(kt + 1) * 64 * HVAL, tid);
            cp_commit();
        }
        const uint32_t kAddr = stb + kOff;
        const uint32_t vAddr = stb + vOff;

        // ---- GEMM1: S = Q' K^T ----
        float s[8][4];
#pragma unroll
        for (int n = 0; n < 8; n++)
#pragma unroll
            for (int e = 0; e < 4; e++) s[n][e] = 0.0f;
#pragma unroll
        for (int t = 0; t < 4; t++) {
            uint32_t ah[4], al[4];
            ldsm_x4(qAddr + t * 32, ah);
            ldsm_x4(qAddr + t * 32 + (AT_QLO - AT_QHI), al);
#pragma unroll
            for (int jp = 0; jp < 4; jp++) {
                uint32_t kh4[4], kl4[4];
                ldsm_x4(kAddr + t * 32 + jp * 16 * PITCH, kh4);
                ldsm_x4(kAddr + t * 32 + (ST_KLO - ST_KHI) + jp * 16 * PITCH,
                        kl4);
#pragma unroll
                for (int jj = 0; jj < 2; jj++) {
                    int n = jp * 2 + jj;
                    mma_bf16(s[n], ah, &kh4[jj * 2]);
                    mma_bf16(s[n], ah, &kl4[jj * 2]);
                    mma_bf16(s[n], al, &kh4[jj * 2]);
                }
            }
        }

        // ---- causal mask (diagonal tile only) ----
        const int rl0 = w * 16 + (lane >> 2);
        if (kt == qt) {
#pragma unroll
            for (int n = 0; n < 8; n++) {
                int c = n * 8 + (lane & 3) * 2;
                if (c > rl0) s[n][0] = -1e30f;
                if (c + 1 > rl0) s[n][1] = -1e30f;
                if (c > rl0 + 8) s[n][2] = -1e30f;
                if (c + 1 > rl0 + 8) s[n][3] = -1e30f;
            }
        }

        // ---- online softmax (per-warp, registers only) ----
        float mx0 = -1e30f, mx1 = -1e30f;
#pragma unroll
        for (int n = 0; n < 8; n++) {
            mx0 = fmaxf(mx0, fmaxf(s[n][0], s[n][1]));
            mx1 = fmaxf(mx1, fmaxf(s[n][2], s[n][3]));
        }
        mx0 = fmaxf(mx0, __shfl_xor_sync(0xffffffffu, mx0, 1));
        mx0 = fmaxf(mx0, __shfl_xor_sync(0xffffffffu, mx0, 2));
        mx1 = fmaxf(mx1, __shfl_xor_sync(0xffffffffu, mx1, 1));
        mx1 = fmaxf(mx1, __shfl_xor_sync(0xffffffffu, mx1, 2));
        float mn0 = fmaxf(m0, mx0), mn1 = fmaxf(m1, mx1);
        float a0 = ex2f(m0 - mn0), a1 = ex2f(m1 - mn1);
        float sum0 = 0.0f, sum1 = 0.0f;
#pragma unroll
        for (int n = 0; n < 8; n++) {
            s[n][0] = ex2f(s[n][0] - mn0);
            s[n][1] = ex2f(s[n][1] - mn0);
            s[n][2] = ex2f(s[n][2] - mn1);
            s[n][3] = ex2f(s[n][3] - mn1);
            sum0 += s[n][0] + s[n][1];
            sum1 += s[n][2] + s[n][3];
        }
        sum0 += __shfl_xor_sync(0xffffffffu, sum0, 1);
        sum0 += __shfl_xor_sync(0xffffffffu, sum0, 2);
        sum1 += __shfl_xor_sync(0xffffffffu, sum1, 1);
        sum1 += __shfl_xor_sync(0xffffffffu, sum1, 2);
        l0 = l0 * a0 + sum0;
        l1 = l1 * a1 + sum1;
        m0 = mn0;
        m1 = mn1;
#pragma unroll
        for (int n = 0; n < 8; n++) {
            oacc[n][0] *= a0;
            oacc[n][1] *= a0;
            oacc[n][2] *= a1;
            oacc[n][3] *= a1;
        }

        // ---- repack P: C-frag -> A-frags (bf16 hi/lo), registers only ----
        uint32_t pah[4][4], pal[4][4];
#pragma unroll
        for (int t = 0; t < 4; t++) {
            pah[t][0] = bfpair(s[2 * t][0], s[2 * t][1]);
            pah[t][1] = bfpair(s[2 * t][2], s[2 * t][3]);
            pah[t][2] = bfpair(s[2 * t + 1][0], s[2 * t + 1][1]);
            pah[t][3] = bfpair(s[2 * t + 1][2], s[2 * t + 1][3]);
            pal[t][0] = bfpair(s[2 * t][0] - bf_lo(pah[t][0]),
                               s[2 * t][1] - bf_hi(pah[t][0]));
            pal[t][1] = bfpair(s[2 * t][2] - bf_lo(pah[t][1]),
                               s[2 * t][3] - bf_hi(pah[t][1]));
            pal[t][2] = bfpair(s[2 * t + 1][0] - bf_lo(pah[t][2]),
                               s[2 * t + 1][1] - bf_hi(pah[t][2]));
            pal[t][3] = bfpair(s[2 * t + 1][2] - bf_lo(pah[t][3]),
                               s[2 * t + 1][3] - bf_hi(pah[t][3]));
        }

        // ---- GEMM2: O += P V ----
#pragma unroll
        for (int t = 0; t < 4; t++) {
#pragma unroll
            for (int jp = 0; jp < 4; jp++) {
                uint32_t vh4[4], vl4[4];
                ldsm_x4_t(vAddr + t * 16 * PITCH + jp * 32, vh4);
                ldsm_x4_t(vAddr + t * 16 * PITCH + (ST_VLO - ST_VHI) + jp * 32,
                          vl4);
#pragma unroll
                for (int jj = 0; jj < 2; jj++) {
                    int n = jp * 2 + jj;
                    mma_bf16(oacc[n], pah[t], &vh4[jj * 2]);
                    mma_bf16(oacc[n], pal[t], &vh4[jj * 2]);
                    mma_bf16(oacc[n], pah[t], &vl4[jj * 2]);
                }
            }
        }

        cp_wait0();
        __syncthreads();
    }

    // ---- epilogue: normalize, write fp32 out [B,T,H] ----
    float i0 = 1.0f / l0, i1 = 1.0f / l1;
    int grow = b * TVAL + qt * 64 + w * 16 + (lane >> 2);
#pragma unroll
    for (int n = 0; n < 8; n++) {
        int col = n * 8 + (lane & 3) * 2;
        *reinterpret_cast<float2*>(&out[(size_t)grow * HVAL + col]) =
            make_float2(oacc[n][0] * i0, oacc[n][1] * i0);
        *reinterpret_cast<float2*>(&out[(size_t)(grow + 8) * HVAL + col]) =
            make_float2(oacc[n][2] * i1, oacc[n][3] * i1);
    }
}

// ============================================================================
// kernel_launch
// ============================================================================
extern "C" void kernel_launch(void* const* d_in, const int* in_sizes, int n_in,
                              void* d_out, int out_size) {
    (void)in_sizes; (void)n_in; (void)out_size;
    const float* x  = (const float*)d_in[0];
    const float* wq = (const float*)d_in[1];
    const float* wk = (const float*)d_in[2];
    const float* wv = (const float*)d_in[3];
    float* out = (float*)d_out;

    conv_w_kernel<<<(192 * CVAL) / 256, 256>>>(wq, wk, wv);

    cudaFuncSetAttribute(qkv_gemm,
                         cudaFuncAttributeMaxDynamicSharedMemorySize, QKV_SMEM);
    qkv_gemm<<<(BVAL * TVAL) / 128, 256, QKV_SMEM>>>(x);

    cudaFuncSetAttribute(attn_hmma,
                         cudaFuncAttributeMaxDynamicSharedMemorySize, ATTN_SMEM);
    dim3 grid(TVAL / 64, BVAL);
    attn_hmma<<<grid, 128, ATTN_SMEM>>>(out);
}